// round 14
// baseline (speedup 1.0000x reference)
#include <cuda_runtime.h>
#include <cuda_fp16.h>
#include <cstdint>

// Problem constants (fixed by the dataset)
#define NI 32
#define H  128
#define NC 64

// Weights stored as m16n8k16 B-fragments, K-pair-packed into uint4:
//   uint4 = { b0(kt=2kp), b1(kt=2kp), b0(kt=2kp+1), b1(kt=2kp+1) }
//   b0 = half2{ B[k0][n], B[k0+1][n] },  k0 = kt*16 + (lane%4)*2,  n = nt*8 + lane/4
#define NFRAG_CAT (16*3*32)   // Wcat: K=96 (x|cond), N=128  -> 1536 uint4
#define NFRAG_W2  (16*4*32)   // W2:   K=128, N=128          -> 2048 uint4
#define NFRAG_W3  (8*4*32)    // W3:   K=128, N=64           -> 1024 uint4
#define NFRAG_TOT (NFRAG_CAT + NFRAG_W2 + NFRAG_W3)          // 4608 uint4 = 73728 B
#define SMEM_BYTES (NFRAG_TOT*16)   // weights ONLY: 73728 = 9 x 8KB granules

__device__ uint4 g_wfrags[NFRAG_TOT];
__device__ float g_bias[2*H + 2*NI];   // [0:128) b1, [128:256) b2, [256:320) b3

static __device__ __forceinline__ unsigned pack2(float a, float b) {
    __half2 h = __floats2half2_rn(a, b);
    return *reinterpret_cast<unsigned*>(&h);
}

// ---------------------------------------------------------------------------
// Pre-pack kernel: apply MADE masks, convert to f16, write fragment order.
// Also stages biases into g_bias.
// ---------------------------------------------------------------------------
__global__ void made_prep(const float* __restrict__ W1, const float* __restrict__ Wc,
                          const float* __restrict__ W2, const float* __restrict__ W3,
                          const float* __restrict__ b1, const float* __restrict__ b2,
                          const float* __restrict__ b3) {
    int idx = blockIdx.x * blockDim.x + threadIdx.x;
    if (idx < 2*H + 2*NI) {
        float v;
        if (idx < H)            v = b1[idx];
        else if (idx < 2*H)     v = b2[idx - H];
        else                    v = b3[idx - 2*H];
        g_bias[idx] = v;
    }
    if (idx >= NFRAG_TOT) return;
    int mat, base, KP;
    if (idx < NFRAG_CAT)                { mat = 0; base = idx;                       KP = 3; }
    else if (idx < NFRAG_CAT+NFRAG_W2)  { mat = 1; base = idx - NFRAG_CAT;           KP = 4; }
    else                                { mat = 2; base = idx - (NFRAG_CAT+NFRAG_W2); KP = 4; }
    int lane = base & 31;
    int kp   = (base >> 5) % KP;
    int nt   = (base >> 5) / KP;
    int t = lane & 3, g = lane >> 2;
    int n = nt * 8 + g;

    float e[8];
#pragma unroll
    for (int i = 0; i < 8; i++) {
        int regsel = i >> 1;
        int kt = 2*kp + (regsel >> 1);
        int k  = kt*16 + (regsel & 1)*8 + 2*t + (i & 1);
        float v;
        if (mat == 0) {
            if (k < NI) v = ((n % 31) >= k) ? W1[n*NI + k] : 0.f;
            else        v = Wc[n*NC + (k - NI)];
        } else if (mat == 1) {
            v = ((n % 31) >= (k % 31)) ? W2[n*H + k] : 0.f;
        } else {
            v = (((n % 32) - 1) >= (k % 31)) ? W3[n*H + k] : 0.f;
        }
        e[i] = v;
    }
    uint4 r;
    r.x = pack2(e[0], e[1]);
    r.y = pack2(e[2], e[3]);
    r.z = pack2(e[4], e[5]);
    r.w = pack2(e[6], e[7]);
    g_wfrags[idx] = r;
}

// ---------------------------------------------------------------------------
// Main fused kernel
// ---------------------------------------------------------------------------
__device__ __forceinline__ void mma16816(float c[4], const unsigned a[4],
                                         unsigned b0, unsigned b1) {
    asm("mma.sync.aligned.m16n8k16.row.col.f32.f16.f16.f32 "
        "{%0,%1,%2,%3}, {%4,%5,%6,%7}, {%8,%9}, {%0,%1,%2,%3};"
        : "+f"(c[0]), "+f"(c[1]), "+f"(c[2]), "+f"(c[3])
        : "r"(a[0]), "r"(a[1]), "r"(a[2]), "r"(a[3]), "r"(b0), "r"(b1));
}

static __device__ __forceinline__ float2 ldg2(const float* p) {
    return __ldg((const float2*)p);
}

// One hidden layer (N=128, relu) for TWO M-tiles sharing each weight load.
// Streams per output K-tile: only 16 fp32 acc live; kt loop not unrolled.
// Biases read from global (L1-resident, 8B per tile).
template<int KP>
__device__ __forceinline__ void layer_relu2(unsigned (&d0)[8][4], unsigned (&d1)[8][4],
                                            const uint4* __restrict__ sB,
                                            const unsigned (*A0)[4],
                                            const unsigned (*A1)[4],
                                            const float* __restrict__ gbias,
                                            int t, int lane) {
#pragma unroll 1
    for (int kt = 0; kt < 8; ++kt) {
        float2 f0 = ldg2(gbias + (2*kt  )*8 + 2*t);
        float2 f1 = ldg2(gbias + (2*kt+1)*8 + 2*t);
        float p00[4] = {f0.x, f0.y, f0.x, f0.y};   // tile0, subtile even
        float p01[4] = {f0.x, f0.y, f0.x, f0.y};   // tile1, subtile even
        float p10[4] = {f1.x, f1.y, f1.x, f1.y};   // tile0, subtile odd
        float p11[4] = {f1.x, f1.y, f1.x, f1.y};   // tile1, subtile odd
#pragma unroll
        for (int kp = 0; kp < KP; ++kp) {
            uint4 w = sB[((2*kt)*KP + kp)*32 + lane];
            mma16816(p00, A0[2*kp],   w.x, w.y);
            mma16816(p00, A0[2*kp+1], w.z, w.w);
            mma16816(p01, A1[2*kp],   w.x, w.y);
            mma16816(p01, A1[2*kp+1], w.z, w.w);
        }
#pragma unroll
        for (int kp = 0; kp < KP; ++kp) {
            uint4 w = sB[((2*kt+1)*KP + kp)*32 + lane];
            mma16816(p10, A0[2*kp],   w.x, w.y);
            mma16816(p10, A0[2*kp+1], w.z, w.w);
            mma16816(p11, A1[2*kp],   w.x, w.y);
            mma16816(p11, A1[2*kp+1], w.z, w.w);
        }
        d0[kt][0] = pack2(fmaxf(p00[0],0.f), fmaxf(p00[1],0.f));
        d0[kt][1] = pack2(fmaxf(p00[2],0.f), fmaxf(p00[3],0.f));
        d0[kt][2] = pack2(fmaxf(p10[0],0.f), fmaxf(p10[1],0.f));
        d0[kt][3] = pack2(fmaxf(p10[2],0.f), fmaxf(p10[3],0.f));
        d1[kt][0] = pack2(fmaxf(p01[0],0.f), fmaxf(p01[1],0.f));
        d1[kt][1] = pack2(fmaxf(p01[2],0.f), fmaxf(p01[3],0.f));
        d1[kt][2] = pack2(fmaxf(p11[0],0.f), fmaxf(p11[1],0.f));
        d1[kt][3] = pack2(fmaxf(p11[2],0.f), fmaxf(p11[3],0.f));
    }
}

#define WARPS 4
#define NITER 4
#define ROWS_PER_CTA (WARPS*NITER*32)   // 512 samples per CTA (32 rows/warp/iter)

__global__ __launch_bounds__(WARPS*32, 3)   // 3 CTAs/SM: smem 3x72KB=216KB, regs<=170
void made_main(const float* __restrict__ x, const float* __restrict__ cond,
               float* __restrict__ out_u, float* __restrict__ out_ld) {
    extern __shared__ unsigned char smem_raw[];
    uint4* sW  = (uint4*)smem_raw;

    for (int i = threadIdx.x; i < NFRAG_TOT; i += blockDim.x) sW[i] = g_wfrags[i];
    __syncthreads();

    const uint4* sWcat = sW;
    const uint4* sW2f  = sW + NFRAG_CAT;
    const uint4* sW3f  = sW + NFRAG_CAT + NFRAG_W2;

    int warp = threadIdx.x >> 5;
    int lane = threadIdx.x & 31;
    int g = lane >> 2, t = lane & 3;
    long long base = (long long)blockIdx.x * ROWS_PER_CTA;

#pragma unroll 1
    for (int it = 0; it < NITER; ++it) {
        long long m0 = base + (long long)(warp*NITER + it) * 32;
        const float* xb = x    + m0 * NI;
        const float* cb = cond + m0 * NC;

        // ---- Load A1 fragments for both M-tiles (x | cond) ----
        unsigned a1[2][6][4];
#pragma unroll
        for (int ti = 0; ti < 2; ++ti) {
            const float* xt = xb + (long long)ti*16*NI;
            const float* ct = cb + (long long)ti*16*NC;
#pragma unroll
            for (int kt = 0; kt < 2; ++kt)
#pragma unroll
                for (int p = 0; p < 4; ++p) {
                    int row = g + (p & 1) * 8;
                    int col = kt*16 + 2*t + (p >> 1) * 8;
                    float2 v = *(const float2*)(xt + row*NI + col);
                    a1[ti][kt][p] = pack2(v.x, v.y);
                }
#pragma unroll
            for (int kt = 2; kt < 6; ++kt)
#pragma unroll
                for (int p = 0; p < 4; ++p) {
                    int row = g + (p & 1) * 8;
                    int col = (kt-2)*16 + 2*t + (p >> 1) * 8;
                    float2 v = *(const float2*)(ct + row*NC + col);
                    a1[ti][kt][p] = pack2(v.x, v.y);
                }
        }

        // ---- Layer 1 -> a2f, Layer 2 -> af3 (shared weight loads) ----
        unsigned a2f[2][8][4];
        layer_relu2<3>(a2f[0], a2f[1], sWcat, a1[0],  a1[1],  g_bias,     t, lane);
        unsigned af3[2][8][4];
        layer_relu2<4>(af3[0], af3[1], sW2f,  a2f[0], a2f[1], g_bias + H, t, lane);

        // ---- Layer 3 + fused epilogue, per output slice nt (m=nt, a=nt+4) ----
        const float* gb3 = g_bias + 2*H;
        float sa[2][2] = {{0.f,0.f},{0.f,0.f}};   // [tile][rowhalf]
#pragma unroll 1
        for (int nt = 0; nt < 4; ++nt) {
            float2 fm = ldg2(gb3 + nt*8 + 2*t);
            float2 fa = ldg2(gb3 + (nt+4)*8 + 2*t);
            float am0[4] = {fm.x, fm.y, fm.x, fm.y};
            float am1[4] = {fm.x, fm.y, fm.x, fm.y};
            float aa0[4] = {fa.x, fa.y, fa.x, fa.y};
            float aa1[4] = {fa.x, fa.y, fa.x, fa.y};
#pragma unroll
            for (int kp = 0; kp < 4; ++kp) {
                uint4 wm = sW3f[(nt*4 + kp)*32 + lane];
                mma16816(am0, af3[0][2*kp],   wm.x, wm.y);
                mma16816(am0, af3[0][2*kp+1], wm.z, wm.w);
                mma16816(am1, af3[1][2*kp],   wm.x, wm.y);
                mma16816(am1, af3[1][2*kp+1], wm.z, wm.w);
            }
#pragma unroll
            for (int kp = 0; kp < 4; ++kp) {
                uint4 wa = sW3f[((nt+4)*4 + kp)*32 + lane];
                mma16816(aa0, af3[0][2*kp],   wa.x, wa.y);
                mma16816(aa0, af3[0][2*kp+1], wa.z, wa.w);
                mma16816(aa1, af3[1][2*kp],   wa.x, wa.y);
                mma16816(aa1, af3[1][2*kp+1], wa.z, wa.w);
            }
            // Epilogue slice: a=clip(a,-5,5); u=(x-m)*exp(-a)
#pragma unroll
            for (int ti = 0; ti < 2; ++ti) {
                const float* xt = xb + (long long)ti*16*NI;
                long long mt = m0 + ti*16;
                const float* am = ti ? am1 : am0;
                const float* aa = ti ? aa1 : aa0;
                float2 x0 = *(const float2*)(xt + g      *NI + nt*8 + 2*t);
                float2 x1 = *(const float2*)(xt + (g + 8)*NI + nt*8 + 2*t);
                float c00 = fminf(fmaxf(aa[0], -5.f), 5.f);
                float c01 = fminf(fmaxf(aa[1], -5.f), 5.f);
                float c10 = fminf(fmaxf(aa[2], -5.f), 5.f);
                float c11 = fminf(fmaxf(aa[3], -5.f), 5.f);
                float2 w0, w1;
                w0.x = (x0.x - am[0]) * __expf(-c00);
                w0.y = (x0.y - am[1]) * __expf(-c01);
                w1.x = (x1.x - am[2]) * __expf(-c10);
                w1.y = (x1.y - am[3]) * __expf(-c11);
                *(float2*)(out_u + (mt + g    )*NI + nt*8 + 2*t) = w0;
                *(float2*)(out_u + (mt + g + 8)*NI + nt*8 + 2*t) = w1;
                sa[ti][0] += c00 + c01;
                sa[ti][1] += c10 + c11;
            }
        }
#pragma unroll
        for (int ti = 0; ti < 2; ++ti) {
            float s0 = sa[ti][0], s1 = sa[ti][1];
            s0 += __shfl_xor_sync(0xffffffffu, s0, 1);
            s0 += __shfl_xor_sync(0xffffffffu, s0, 2);
            s1 += __shfl_xor_sync(0xffffffffu, s1, 1);
            s1 += __shfl_xor_sync(0xffffffffu, s1, 2);
            if (t == 0) {
                out_ld[m0 + ti*16 + g]     = -s0;
                out_ld[m0 + ti*16 + g + 8] = -s1;
            }
        }
    }
}

// ---------------------------------------------------------------------------
// Launch
// ---------------------------------------------------------------------------
extern "C" void kernel_launch(void* const* d_in, const int* in_sizes, int n_in,
                              void* d_out, int out_size) {
    const float* x    = (const float*)d_in[0];
    const float* cond = (const float*)d_in[1];
    const float* W1   = (const float*)d_in[2];
    const float* b1   = (const float*)d_in[3];
    const float* Wc   = (const float*)d_in[4];
    const float* W2   = (const float*)d_in[5];
    const float* b2   = (const float*)d_in[6];
    const float* W3   = (const float*)d_in[7];
    const float* b3   = (const float*)d_in[8];

    long long B = (long long)in_sizes[0] / NI;
    float* out_u  = (float*)d_out;
    float* out_ld = out_u + B * NI;

    // Pre-pack masked weights + biases (tiny kernel, same stream)
    made_prep<<<(NFRAG_TOT + 127) / 128, 128>>>(W1, Wc, W2, W3, b1, b2, b3);

    cudaFuncSetAttribute(made_main, cudaFuncAttributeMaxDynamicSharedMemorySize,
                         SMEM_BYTES);

    int nCTA = (int)(B / ROWS_PER_CTA);
    made_main<<<nCTA, WARPS*32, SMEM_BYTES>>>(x, cond, out_u, out_ld);
}

// round 15
// speedup vs baseline: 1.3214x; 1.3214x over previous
#include <cuda_runtime.h>
#include <cuda_fp16.h>
#include <cstdint>

// Problem constants (fixed by the dataset)
#define NI 32
#define H  128
#define NC 64

// Weights stored as m16n8k16 B-fragments, K-pair-packed into uint4:
//   uint4 = { b0(kt=2kp), b1(kt=2kp), b0(kt=2kp+1), b1(kt=2kp+1) }
//   b0 = half2{ B[k0][n], B[k0+1][n] },  k0 = kt*16 + (lane%4)*2,  n = nt*8 + lane/4
#define NFRAG_CAT (16*3*32)   // Wcat: K=96 (x|cond), N=128  -> 1536 uint4
#define NFRAG_W2  (16*4*32)   // W2:   K=128, N=128          -> 2048 uint4
#define NFRAG_W3  (8*4*32)    // W3:   K=128, N=64           -> 1024 uint4
#define NFRAG_TOT (NFRAG_CAT + NFRAG_W2 + NFRAG_W3)          // 4608 uint4 = 73728 B
#define SMEM_BYTES (NFRAG_TOT*16 + (H + H + 2*NI)*4)         // + biases = 75008 B

__device__ uint4 g_wfrags[NFRAG_TOT];

static __device__ __forceinline__ unsigned pack2(float a, float b) {
    __half2 h = __floats2half2_rn(a, b);
    return *reinterpret_cast<unsigned*>(&h);
}

// ---------------------------------------------------------------------------
// Pre-pack kernel: apply MADE masks, convert to f16, write fragment order.
// ---------------------------------------------------------------------------
__global__ void made_prep(const float* __restrict__ W1, const float* __restrict__ Wc,
                          const float* __restrict__ W2, const float* __restrict__ W3) {
    int idx = blockIdx.x * blockDim.x + threadIdx.x;
    if (idx >= NFRAG_TOT) return;
    int mat, base, KP;
    if (idx < NFRAG_CAT)                { mat = 0; base = idx;                       KP = 3; }
    else if (idx < NFRAG_CAT+NFRAG_W2)  { mat = 1; base = idx - NFRAG_CAT;           KP = 4; }
    else                                { mat = 2; base = idx - (NFRAG_CAT+NFRAG_W2); KP = 4; }
    int lane = base & 31;
    int kp   = (base >> 5) % KP;
    int nt   = (base >> 5) / KP;
    int t = lane & 3, g = lane >> 2;
    int n = nt * 8 + g;

    float e[8];
#pragma unroll
    for (int i = 0; i < 8; i++) {
        int regsel = i >> 1;
        int kt = 2*kp + (regsel >> 1);
        int k  = kt*16 + (regsel & 1)*8 + 2*t + (i & 1);
        float v;
        if (mat == 0) {
            if (k < NI) v = ((n % 31) >= k) ? W1[n*NI + k] : 0.f;
            else        v = Wc[n*NC + (k - NI)];
        } else if (mat == 1) {
            v = ((n % 31) >= (k % 31)) ? W2[n*H + k] : 0.f;
        } else {
            v = (((n % 32) - 1) >= (k % 31)) ? W3[n*H + k] : 0.f;
        }
        e[i] = v;
    }
    uint4 r;
    r.x = pack2(e[0], e[1]);
    r.y = pack2(e[2], e[3]);
    r.z = pack2(e[4], e[5]);
    r.w = pack2(e[6], e[7]);
    g_wfrags[idx] = r;
}

// ---------------------------------------------------------------------------
// Main fused kernel
// ---------------------------------------------------------------------------
__device__ __forceinline__ void mma16816(float c[4], const unsigned a[4],
                                         unsigned b0, unsigned b1) {
    asm("mma.sync.aligned.m16n8k16.row.col.f32.f16.f16.f32 "
        "{%0,%1,%2,%3}, {%4,%5,%6,%7}, {%8,%9}, {%0,%1,%2,%3};"
        : "+f"(c[0]), "+f"(c[1]), "+f"(c[2]), "+f"(c[3])
        : "r"(a[0]), "r"(a[1]), "r"(a[2]), "r"(a[3]), "r"(b0), "r"(b1));
}

// One hidden layer (N=128, relu) for TWO M-tiles sharing each weight load.
// Streams per output K-tile: only 16 fp32 acc live; kt loop not unrolled.
template<int KP>
__device__ __forceinline__ void layer_relu2(unsigned (&d0)[8][4], unsigned (&d1)[8][4],
                                            const uint4* __restrict__ sB,
                                            const unsigned (*A0)[4],
                                            const unsigned (*A1)[4],
                                            const float* __restrict__ sbias,
                                            int t, int lane) {
#pragma unroll 1
    for (int kt = 0; kt < 8; ++kt) {
        float2 f0 = *(const float2*)(sbias + (2*kt  )*8 + 2*t);
        float2 f1 = *(const float2*)(sbias + (2*kt+1)*8 + 2*t);
        float p00[4] = {f0.x, f0.y, f0.x, f0.y};   // tile0, subtile even
        float p01[4] = {f0.x, f0.y, f0.x, f0.y};   // tile1, subtile even
        float p10[4] = {f1.x, f1.y, f1.x, f1.y};   // tile0, subtile odd
        float p11[4] = {f1.x, f1.y, f1.x, f1.y};   // tile1, subtile odd
#pragma unroll
        for (int kp = 0; kp < KP; ++kp) {
            uint4 w = sB[((2*kt)*KP + kp)*32 + lane];
            mma16816(p00, A0[2*kp],   w.x, w.y);
            mma16816(p00, A0[2*kp+1], w.z, w.w);
            mma16816(p01, A1[2*kp],   w.x, w.y);
            mma16816(p01, A1[2*kp+1], w.z, w.w);
        }
#pragma unroll
        for (int kp = 0; kp < KP; ++kp) {
            uint4 w = sB[((2*kt+1)*KP + kp)*32 + lane];
            mma16816(p10, A0[2*kp],   w.x, w.y);
            mma16816(p10, A0[2*kp+1], w.z, w.w);
            mma16816(p11, A1[2*kp],   w.x, w.y);
            mma16816(p11, A1[2*kp+1], w.z, w.w);
        }
        d0[kt][0] = pack2(fmaxf(p00[0],0.f), fmaxf(p00[1],0.f));
        d0[kt][1] = pack2(fmaxf(p00[2],0.f), fmaxf(p00[3],0.f));
        d0[kt][2] = pack2(fmaxf(p10[0],0.f), fmaxf(p10[1],0.f));
        d0[kt][3] = pack2(fmaxf(p10[2],0.f), fmaxf(p10[3],0.f));
        d1[kt][0] = pack2(fmaxf(p01[0],0.f), fmaxf(p01[1],0.f));
        d1[kt][1] = pack2(fmaxf(p01[2],0.f), fmaxf(p01[3],0.f));
        d1[kt][2] = pack2(fmaxf(p11[0],0.f), fmaxf(p11[1],0.f));
        d1[kt][3] = pack2(fmaxf(p11[2],0.f), fmaxf(p11[3],0.f));
    }
}

#define WARPS 12
#define THREADS (WARPS*32)
#define GRID 148    // one CTA per SM, single wave; warps grid-stride over chunks

__global__ __launch_bounds__(THREADS, 1)   // 65536/384 = 170 regs/thread cap
void made_main(const float* __restrict__ x, const float* __restrict__ cond,
               const float* __restrict__ b1, const float* __restrict__ b2,
               const float* __restrict__ b3,
               float* __restrict__ out_u, float* __restrict__ out_ld,
               int nChunks) {
    extern __shared__ unsigned char smem_raw[];
    uint4* sW  = (uint4*)smem_raw;
    float* sb1 = (float*)(sW + NFRAG_TOT);
    float* sb2 = sb1 + H;
    float* sb3 = sb2 + H;

    for (int i = threadIdx.x; i < NFRAG_TOT; i += blockDim.x) sW[i] = g_wfrags[i];
    if (threadIdx.x < H)    { sb1[threadIdx.x] = b1[threadIdx.x];
                              sb2[threadIdx.x] = b2[threadIdx.x]; }
    if (threadIdx.x < 2*NI)   sb3[threadIdx.x] = b3[threadIdx.x];
    __syncthreads();

    const uint4* sWcat = sW;
    const uint4* sW2f  = sW + NFRAG_CAT;
    const uint4* sW3f  = sW + NFRAG_CAT + NFRAG_W2;

    int warp = threadIdx.x >> 5;
    int lane = threadIdx.x & 31;
    int g = lane >> 2, t = lane & 3;

    int gwarp  = blockIdx.x * WARPS + warp;
    int wstride = gridDim.x * WARPS;

#pragma unroll 1
    for (int chunk = gwarp; chunk < nChunks; chunk += wstride) {
        long long m0 = (long long)chunk * 32;
        const float* xb = x    + m0 * NI;
        const float* cb = cond + m0 * NC;

        // ---- Load A1 fragments for both M-tiles (x | cond) ----
        unsigned a1[2][6][4];
#pragma unroll
        for (int ti = 0; ti < 2; ++ti) {
            const float* xt = xb + (long long)ti*16*NI;
            const float* ct = cb + (long long)ti*16*NC;
#pragma unroll
            for (int kt = 0; kt < 2; ++kt)
#pragma unroll
                for (int p = 0; p < 4; ++p) {
                    int row = g + (p & 1) * 8;
                    int col = kt*16 + 2*t + (p >> 1) * 8;
                    float2 v = *(const float2*)(xt + row*NI + col);
                    a1[ti][kt][p] = pack2(v.x, v.y);
                }
#pragma unroll
            for (int kt = 2; kt < 6; ++kt)
#pragma unroll
                for (int p = 0; p < 4; ++p) {
                    int row = g + (p & 1) * 8;
                    int col = (kt-2)*16 + 2*t + (p >> 1) * 8;
                    float2 v = *(const float2*)(ct + row*NC + col);
                    a1[ti][kt][p] = pack2(v.x, v.y);
                }
        }

        // ---- Layer 1 -> a2f, Layer 2 -> af3 (shared weight loads) ----
        unsigned a2f[2][8][4];
        layer_relu2<3>(a2f[0], a2f[1], sWcat, a1[0],  a1[1],  sb1, t, lane);
        unsigned af3[2][8][4];
        layer_relu2<4>(af3[0], af3[1], sW2f,  a2f[0], a2f[1], sb2, t, lane);

        // ---- Layer 3 + fused epilogue, per output slice nt (m=nt, a=nt+4) ----
        float sa[2][2] = {{0.f,0.f},{0.f,0.f}};   // [tile][rowhalf]
#pragma unroll 1
        for (int nt = 0; nt < 4; ++nt) {
            float2 fm = *(const float2*)(sb3 + nt*8 + 2*t);
            float2 fa = *(const float2*)(sb3 + (nt+4)*8 + 2*t);
            float am0[4] = {fm.x, fm.y, fm.x, fm.y};
            float am1[4] = {fm.x, fm.y, fm.x, fm.y};
            float aa0[4] = {fa.x, fa.y, fa.x, fa.y};
            float aa1[4] = {fa.x, fa.y, fa.x, fa.y};
#pragma unroll
            for (int kp = 0; kp < 4; ++kp) {
                uint4 wm = sW3f[(nt*4 + kp)*32 + lane];
                mma16816(am0, af3[0][2*kp],   wm.x, wm.y);
                mma16816(am0, af3[0][2*kp+1], wm.z, wm.w);
                mma16816(am1, af3[1][2*kp],   wm.x, wm.y);
                mma16816(am1, af3[1][2*kp+1], wm.z, wm.w);
            }
#pragma unroll
            for (int kp = 0; kp < 4; ++kp) {
                uint4 wa = sW3f[((nt+4)*4 + kp)*32 + lane];
                mma16816(aa0, af3[0][2*kp],   wa.x, wa.y);
                mma16816(aa0, af3[0][2*kp+1], wa.z, wa.w);
                mma16816(aa1, af3[1][2*kp],   wa.x, wa.y);
                mma16816(aa1, af3[1][2*kp+1], wa.z, wa.w);
            }
            // Epilogue slice: a=clip(a,-5,5); u=(x-m)*exp(-a)
#pragma unroll
            for (int ti = 0; ti < 2; ++ti) {
                const float* xt = xb + (long long)ti*16*NI;
                long long mt = m0 + ti*16;
                const float* am = ti ? am1 : am0;
                const float* aa = ti ? aa1 : aa0;
                float2 x0 = *(const float2*)(xt + g      *NI + nt*8 + 2*t);
                float2 x1 = *(const float2*)(xt + (g + 8)*NI + nt*8 + 2*t);
                float c00 = fminf(fmaxf(aa[0], -5.f), 5.f);
                float c01 = fminf(fmaxf(aa[1], -5.f), 5.f);
                float c10 = fminf(fmaxf(aa[2], -5.f), 5.f);
                float c11 = fminf(fmaxf(aa[3], -5.f), 5.f);
                float2 w0, w1;
                w0.x = (x0.x - am[0]) * __expf(-c00);
                w0.y = (x0.y - am[1]) * __expf(-c01);
                w1.x = (x1.x - am[2]) * __expf(-c10);
                w1.y = (x1.y - am[3]) * __expf(-c11);
                *(float2*)(out_u + (mt + g    )*NI + nt*8 + 2*t) = w0;
                *(float2*)(out_u + (mt + g + 8)*NI + nt*8 + 2*t) = w1;
                sa[ti][0] += c00 + c01;
                sa[ti][1] += c10 + c11;
            }
        }
#pragma unroll
        for (int ti = 0; ti < 2; ++ti) {
            float s0 = sa[ti][0], s1 = sa[ti][1];
            s0 += __shfl_xor_sync(0xffffffffu, s0, 1);
            s0 += __shfl_xor_sync(0xffffffffu, s0, 2);
            s1 += __shfl_xor_sync(0xffffffffu, s1, 1);
            s1 += __shfl_xor_sync(0xffffffffu, s1, 2);
            if (t == 0) {
                out_ld[m0 + ti*16 + g]     = -s0;
                out_ld[m0 + ti*16 + g + 8] = -s1;
            }
        }
    }
}

// ---------------------------------------------------------------------------
// Launch
// ---------------------------------------------------------------------------
extern "C" void kernel_launch(void* const* d_in, const int* in_sizes, int n_in,
                              void* d_out, int out_size) {
    const float* x    = (const float*)d_in[0];
    const float* cond = (const float*)d_in[1];
    const float* W1   = (const float*)d_in[2];
    const float* b1   = (const float*)d_in[3];
    const float* Wc   = (const float*)d_in[4];
    const float* W2   = (const float*)d_in[5];
    const float* b2   = (const float*)d_in[6];
    const float* W3   = (const float*)d_in[7];
    const float* b3   = (const float*)d_in[8];

    long long B = (long long)in_sizes[0] / NI;
    float* out_u  = (float*)d_out;
    float* out_ld = out_u + B * NI;
    int nChunks = (int)(B / 32);

    // Pre-pack masked weights into fragment order (tiny kernel, same stream)
    made_prep<<<(NFRAG_TOT + 127) / 128, 128>>>(W1, Wc, W2, W3);

    cudaFuncSetAttribute(made_main, cudaFuncAttributeMaxDynamicSharedMemorySize,
                         SMEM_BYTES);

    made_main<<<GRID, THREADS, SMEM_BYTES>>>(x, cond, b1, b2, b3,
                                             out_u, out_ld, nChunks);
}

// round 16
// speedup vs baseline: 1.4238x; 1.0775x over previous
#include <cuda_runtime.h>
#include <cuda_fp16.h>
#include <cstdint>

// Problem constants (fixed by the dataset)
#define NI 32
#define H  128
#define NC 64

// Weights stored as m16n8k16 B-fragments, K-pair-packed into uint4:
//   uint4 = { b0(kt=2kp), b1(kt=2kp), b0(kt=2kp+1), b1(kt=2kp+1) }
//   b0 = half2{ B[k0][n], B[k0+1][n] },  k0 = kt*16 + (lane%4)*2,  n = nt*8 + lane/4
#define NFRAG_CAT (16*3*32)   // Wcat: K=96 (x|cond), N=128  -> 1536 uint4
#define NFRAG_W2  (16*4*32)   // W2:   K=128, N=128          -> 2048 uint4
#define NFRAG_W3  (8*4*32)    // W3:   K=128, N=64           -> 1024 uint4
#define NFRAG_TOT (NFRAG_CAT + NFRAG_W2 + NFRAG_W3)          // 4608 uint4 = 73728 B
#define SMEM_BYTES (NFRAG_TOT*16 + (H + H + 2*NI)*4)         // + biases = 75008 B

__device__ uint4 g_wfrags[NFRAG_TOT];

static __device__ __forceinline__ unsigned pack2(float a, float b) {
    __half2 h = __floats2half2_rn(a, b);
    return *reinterpret_cast<unsigned*>(&h);
}

// ---------------------------------------------------------------------------
// Pre-pack kernel: apply MADE masks, convert to f16, write fragment order.
// ---------------------------------------------------------------------------
__global__ void made_prep(const float* __restrict__ W1, const float* __restrict__ Wc,
                          const float* __restrict__ W2, const float* __restrict__ W3) {
    int idx = blockIdx.x * blockDim.x + threadIdx.x;
    if (idx >= NFRAG_TOT) return;
    int mat, base, KP;
    if (idx < NFRAG_CAT)                { mat = 0; base = idx;                       KP = 3; }
    else if (idx < NFRAG_CAT+NFRAG_W2)  { mat = 1; base = idx - NFRAG_CAT;           KP = 4; }
    else                                { mat = 2; base = idx - (NFRAG_CAT+NFRAG_W2); KP = 4; }
    int lane = base & 31;
    int kp   = (base >> 5) % KP;
    int nt   = (base >> 5) / KP;
    int t = lane & 3, g = lane >> 2;
    int n = nt * 8 + g;

    float e[8];
#pragma unroll
    for (int i = 0; i < 8; i++) {
        int regsel = i >> 1;
        int kt = 2*kp + (regsel >> 1);
        int k  = kt*16 + (regsel & 1)*8 + 2*t + (i & 1);
        float v;
        if (mat == 0) {
            if (k < NI) v = ((n % 31) >= k) ? W1[n*NI + k] : 0.f;
            else        v = Wc[n*NC + (k - NI)];
        } else if (mat == 1) {
            v = ((n % 31) >= (k % 31)) ? W2[n*H + k] : 0.f;
        } else {
            v = (((n % 32) - 1) >= (k % 31)) ? W3[n*H + k] : 0.f;
        }
        e[i] = v;
    }
    uint4 r;
    r.x = pack2(e[0], e[1]);
    r.y = pack2(e[2], e[3]);
    r.z = pack2(e[4], e[5]);
    r.w = pack2(e[6], e[7]);
    g_wfrags[idx] = r;
}

// ---------------------------------------------------------------------------
// Main fused kernel
// ---------------------------------------------------------------------------
__device__ __forceinline__ void mma16816(float c[4], const unsigned a[4],
                                         unsigned b0, unsigned b1) {
    asm("mma.sync.aligned.m16n8k16.row.col.f32.f16.f16.f32 "
        "{%0,%1,%2,%3}, {%4,%5,%6,%7}, {%8,%9}, {%0,%1,%2,%3};"
        : "+f"(c[0]), "+f"(c[1]), "+f"(c[2]), "+f"(c[3])
        : "r"(a[0]), "r"(a[1]), "r"(a[2]), "r"(a[3]), "r"(b0), "r"(b1));
}

// One hidden layer (N=128, relu) for TWO M-tiles sharing each weight load.
// Streams per output K-tile: only 16 fp32 acc live; kt loop not unrolled.
template<int KP>
__device__ __forceinline__ void layer_relu2(unsigned (&d0)[8][4], unsigned (&d1)[8][4],
                                            const uint4* __restrict__ sB,
                                            const unsigned (*A0)[4],
                                            const unsigned (*A1)[4],
                                            const float* __restrict__ sbias,
                                            int t, int lane) {
#pragma unroll 1
    for (int kt = 0; kt < 8; ++kt) {
        float2 f0 = *(const float2*)(sbias + (2*kt  )*8 + 2*t);
        float2 f1 = *(const float2*)(sbias + (2*kt+1)*8 + 2*t);
        float p00[4] = {f0.x, f0.y, f0.x, f0.y};   // tile0, subtile even
        float p01[4] = {f0.x, f0.y, f0.x, f0.y};   // tile1, subtile even
        float p10[4] = {f1.x, f1.y, f1.x, f1.y};   // tile0, subtile odd
        float p11[4] = {f1.x, f1.y, f1.x, f1.y};   // tile1, subtile odd
#pragma unroll
        for (int kp = 0; kp < KP; ++kp) {
            uint4 w = sB[((2*kt)*KP + kp)*32 + lane];
            mma16816(p00, A0[2*kp],   w.x, w.y);
            mma16816(p00, A0[2*kp+1], w.z, w.w);
            mma16816(p01, A1[2*kp],   w.x, w.y);
            mma16816(p01, A1[2*kp+1], w.z, w.w);
        }
#pragma unroll
        for (int kp = 0; kp < KP; ++kp) {
            uint4 w = sB[((2*kt+1)*KP + kp)*32 + lane];
            mma16816(p10, A0[2*kp],   w.x, w.y);
            mma16816(p10, A0[2*kp+1], w.z, w.w);
            mma16816(p11, A1[2*kp],   w.x, w.y);
            mma16816(p11, A1[2*kp+1], w.z, w.w);
        }
        d0[kt][0] = pack2(fmaxf(p00[0],0.f), fmaxf(p00[1],0.f));
        d0[kt][1] = pack2(fmaxf(p00[2],0.f), fmaxf(p00[3],0.f));
        d0[kt][2] = pack2(fmaxf(p10[0],0.f), fmaxf(p10[1],0.f));
        d0[kt][3] = pack2(fmaxf(p10[2],0.f), fmaxf(p10[3],0.f));
        d1[kt][0] = pack2(fmaxf(p01[0],0.f), fmaxf(p01[1],0.f));
        d1[kt][1] = pack2(fmaxf(p01[2],0.f), fmaxf(p01[3],0.f));
        d1[kt][2] = pack2(fmaxf(p11[0],0.f), fmaxf(p11[1],0.f));
        d1[kt][3] = pack2(fmaxf(p11[2],0.f), fmaxf(p11[3],0.f));
    }
}

#define WARPS 16
#define THREADS (WARPS*32)
#define GRID 148    // one CTA per SM, single wave; warps grid-stride over chunks

__global__ __launch_bounds__(THREADS, 1)   // 65536/512 = 128 regs/thread cap
void made_main(const float* __restrict__ x, const float* __restrict__ cond,
               const float* __restrict__ b1, const float* __restrict__ b2,
               const float* __restrict__ b3,
               float* __restrict__ out_u, float* __restrict__ out_ld,
               int nChunks) {
    extern __shared__ unsigned char smem_raw[];
    uint4* sW  = (uint4*)smem_raw;
    float* sb1 = (float*)(sW + NFRAG_TOT);
    float* sb2 = sb1 + H;
    float* sb3 = sb2 + H;

    for (int i = threadIdx.x; i < NFRAG_TOT; i += blockDim.x) sW[i] = g_wfrags[i];
    if (threadIdx.x < H)    { sb1[threadIdx.x] = b1[threadIdx.x];
                              sb2[threadIdx.x] = b2[threadIdx.x]; }
    if (threadIdx.x < 2*NI)   sb3[threadIdx.x] = b3[threadIdx.x];
    __syncthreads();

    const uint4* sWcat = sW;
    const uint4* sW2f  = sW + NFRAG_CAT;
    const uint4* sW3f  = sW + NFRAG_CAT + NFRAG_W2;

    int warp = threadIdx.x >> 5;
    int lane = threadIdx.x & 31;
    int g = lane >> 2, t = lane & 3;

    int gwarp   = blockIdx.x * WARPS + warp;
    int wstride = gridDim.x * WARPS;

    // All index arithmetic in 32-bit: max offset = B*NC = 2^19*64 = 2^25 floats.
#pragma unroll 1
    for (int chunk = gwarp; chunk < nChunks; chunk += wstride) {
        int m0   = chunk * 32;           // sample row base (< 2^19)
        int xoff = m0 * NI;              // < 2^24
        int coff = m0 * NC;              // < 2^25
        const float* xb = x    + xoff;
        const float* cb = cond + coff;

        // ---- Load A1 fragments for both M-tiles (x | cond) ----
        unsigned a1[2][6][4];
#pragma unroll
        for (int ti = 0; ti < 2; ++ti) {
            const float* xt = xb + ti*16*NI;
            const float* ct = cb + ti*16*NC;
#pragma unroll
            for (int kt = 0; kt < 2; ++kt)
#pragma unroll
                for (int p = 0; p < 4; ++p) {
                    int row = g + (p & 1) * 8;
                    int col = kt*16 + 2*t + (p >> 1) * 8;
                    float2 v = *(const float2*)(xt + row*NI + col);
                    a1[ti][kt][p] = pack2(v.x, v.y);
                }
#pragma unroll
            for (int kt = 2; kt < 6; ++kt)
#pragma unroll
                for (int p = 0; p < 4; ++p) {
                    int row = g + (p & 1) * 8;
                    int col = (kt-2)*16 + 2*t + (p >> 1) * 8;
                    float2 v = *(const float2*)(ct + row*NC + col);
                    a1[ti][kt][p] = pack2(v.x, v.y);
                }
        }

        // ---- Layer 1 -> a2f, Layer 2 -> af3 (shared weight loads) ----
        unsigned a2f[2][8][4];
        layer_relu2<3>(a2f[0], a2f[1], sWcat, a1[0],  a1[1],  sb1, t, lane);
        unsigned af3[2][8][4];
        layer_relu2<4>(af3[0], af3[1], sW2f,  a2f[0], a2f[1], sb2, t, lane);

        // ---- Layer 3 + fused epilogue, per output slice nt (m=nt, a=nt+4) ----
        float sa[2][2] = {{0.f,0.f},{0.f,0.f}};   // [tile][rowhalf]
#pragma unroll 1
        for (int nt = 0; nt < 4; ++nt) {
            float2 fm = *(const float2*)(sb3 + nt*8 + 2*t);
            float2 fa = *(const float2*)(sb3 + (nt+4)*8 + 2*t);
            float am0[4] = {fm.x, fm.y, fm.x, fm.y};
            float am1[4] = {fm.x, fm.y, fm.x, fm.y};
            float aa0[4] = {fa.x, fa.y, fa.x, fa.y};
            float aa1[4] = {fa.x, fa.y, fa.x, fa.y};
#pragma unroll
            for (int kp = 0; kp < 4; ++kp) {
                uint4 wm = sW3f[(nt*4 + kp)*32 + lane];
                mma16816(am0, af3[0][2*kp],   wm.x, wm.y);
                mma16816(am0, af3[0][2*kp+1], wm.z, wm.w);
                mma16816(am1, af3[1][2*kp],   wm.x, wm.y);
                mma16816(am1, af3[1][2*kp+1], wm.z, wm.w);
            }
#pragma unroll
            for (int kp = 0; kp < 4; ++kp) {
                uint4 wa = sW3f[((nt+4)*4 + kp)*32 + lane];
                mma16816(aa0, af3[0][2*kp],   wa.x, wa.y);
                mma16816(aa0, af3[0][2*kp+1], wa.z, wa.w);
                mma16816(aa1, af3[1][2*kp],   wa.x, wa.y);
                mma16816(aa1, af3[1][2*kp+1], wa.z, wa.w);
            }
            // Epilogue slice: a=clip(a,-5,5); u=(x-m)*exp(-a)
#pragma unroll
            for (int ti = 0; ti < 2; ++ti) {
                const float* xt = xb + ti*16*NI;
                int obase = xoff + ti*16*NI;
                const float* am = ti ? am1 : am0;
                const float* aa = ti ? aa1 : aa0;
                float2 x0 = *(const float2*)(xt + g      *NI + nt*8 + 2*t);
                float2 x1 = *(const float2*)(xt + (g + 8)*NI + nt*8 + 2*t);
                float c00 = fminf(fmaxf(aa[0], -5.f), 5.f);
                float c01 = fminf(fmaxf(aa[1], -5.f), 5.f);
                float c10 = fminf(fmaxf(aa[2], -5.f), 5.f);
                float c11 = fminf(fmaxf(aa[3], -5.f), 5.f);
                float2 w0, w1;
                w0.x = (x0.x - am[0]) * __expf(-c00);
                w0.y = (x0.y - am[1]) * __expf(-c01);
                w1.x = (x1.x - am[2]) * __expf(-c10);
                w1.y = (x1.y - am[3]) * __expf(-c11);
                *(float2*)(out_u + obase + g      *NI + nt*8 + 2*t) = w0;
                *(float2*)(out_u + obase + (g + 8)*NI + nt*8 + 2*t) = w1;
                sa[ti][0] += c00 + c01;
                sa[ti][1] += c10 + c11;
            }
        }
#pragma unroll
        for (int ti = 0; ti < 2; ++ti) {
            float s0 = sa[ti][0], s1 = sa[ti][1];
            s0 += __shfl_xor_sync(0xffffffffu, s0, 1);
            s0 += __shfl_xor_sync(0xffffffffu, s0, 2);
            s1 += __shfl_xor_sync(0xffffffffu, s1, 1);
            s1 += __shfl_xor_sync(0xffffffffu, s1, 2);
            if (t == 0) {
                out_ld[m0 + ti*16 + g]     = -s0;
                out_ld[m0 + ti*16 + g + 8] = -s1;
            }
        }
    }
}

// ---------------------------------------------------------------------------
// Launch
// ---------------------------------------------------------------------------
extern "C" void kernel_launch(void* const* d_in, const int* in_sizes, int n_in,
                              void* d_out, int out_size) {
    const float* x    = (const float*)d_in[0];
    const float* cond = (const float*)d_in[1];
    const float* W1   = (const float*)d_in[2];
    const float* b1   = (const float*)d_in[3];
    const float* Wc   = (const float*)d_in[4];
    const float* W2   = (const float*)d_in[5];
    const float* b2   = (const float*)d_in[6];
    const float* W3   = (const float*)d_in[7];
    const float* b3   = (const float*)d_in[8];

    long long B = (long long)in_sizes[0] / NI;
    float* out_u  = (float*)d_out;
    float* out_ld = out_u + B * NI;
    int nChunks = (int)(B / 32);

    // Pre-pack masked weights into fragment order (tiny kernel, same stream)
    made_prep<<<(NFRAG_TOT + 127) / 128, 128>>>(W1, Wc, W2, W3);

    cudaFuncSetAttribute(made_main, cudaFuncAttributeMaxDynamicSharedMemorySize,
                         SMEM_BYTES);

    made_main<<<GRID, THREADS, SMEM_BYTES>>>(x, cond, b1, b2, b3,
                                             out_u, out_ld, nChunks);
}

// round 17
// speedup vs baseline: 1.4261x; 1.0016x over previous
#include <cuda_runtime.h>
#include <cuda_fp16.h>
#include <cstdint>

// Problem constants (fixed by the dataset)
#define NI 32
#define H  128
#define NC 64

// Weights stored as m16n8k16 B-fragments, K-pair-packed into uint4:
//   uint4 = { b0(kt=2kp), b1(kt=2kp), b0(kt=2kp+1), b1(kt=2kp+1) }
//   b0 = half2{ B[k0][n], B[k0+1][n] },  k0 = kt*16 + (lane%4)*2,  n = nt*8 + lane/4
#define NFRAG_CAT (16*3*32)   // Wcat: K=96 (x|cond), N=128  -> 1536 uint4
#define NFRAG_W2  (16*4*32)   // W2:   K=128, N=128          -> 2048 uint4
#define NFRAG_W3  (8*4*32)    // W3:   K=128, N=64           -> 1024 uint4
#define NFRAG_TOT (NFRAG_CAT + NFRAG_W2 + NFRAG_W3)          // 4608 uint4 = 73728 B
#define SMEM_BYTES (NFRAG_TOT*16 + (H + H + 2*NI)*4)         // + biases = 75008 B

__device__ uint4 g_wfrags[NFRAG_TOT];

static __device__ __forceinline__ unsigned pack2(float a, float b) {
    __half2 h = __floats2half2_rn(a, b);
    return *reinterpret_cast<unsigned*>(&h);
}

// ---------------------------------------------------------------------------
// Pre-pack kernel: apply MADE masks, convert to f16, write fragment order.
// ---------------------------------------------------------------------------
__global__ void made_prep(const float* __restrict__ W1, const float* __restrict__ Wc,
                          const float* __restrict__ W2, const float* __restrict__ W3) {
    int idx = blockIdx.x * blockDim.x + threadIdx.x;
    if (idx >= NFRAG_TOT) return;
    int mat, base, KP;
    if (idx < NFRAG_CAT)                { mat = 0; base = idx;                       KP = 3; }
    else if (idx < NFRAG_CAT+NFRAG_W2)  { mat = 1; base = idx - NFRAG_CAT;           KP = 4; }
    else                                { mat = 2; base = idx - (NFRAG_CAT+NFRAG_W2); KP = 4; }
    int lane = base & 31;
    int kp   = (base >> 5) % KP;
    int nt   = (base >> 5) / KP;
    int t = lane & 3, g = lane >> 2;
    int n = nt * 8 + g;

    float e[8];
#pragma unroll
    for (int i = 0; i < 8; i++) {
        int regsel = i >> 1;
        int kt = 2*kp + (regsel >> 1);
        int k  = kt*16 + (regsel & 1)*8 + 2*t + (i & 1);
        float v;
        if (mat == 0) {
            if (k < NI) v = ((n % 31) >= k) ? W1[n*NI + k] : 0.f;
            else        v = Wc[n*NC + (k - NI)];
        } else if (mat == 1) {
            v = ((n % 31) >= (k % 31)) ? W2[n*H + k] : 0.f;
        } else {
            v = (((n % 32) - 1) >= (k % 31)) ? W3[n*H + k] : 0.f;
        }
        e[i] = v;
    }
    uint4 r;
    r.x = pack2(e[0], e[1]);
    r.y = pack2(e[2], e[3]);
    r.z = pack2(e[4], e[5]);
    r.w = pack2(e[6], e[7]);
    g_wfrags[idx] = r;
}

// ---------------------------------------------------------------------------
// Main fused kernel
// ---------------------------------------------------------------------------
__device__ __forceinline__ void mma16816(float c[4], const unsigned a[4],
                                         unsigned b0, unsigned b1) {
    asm("mma.sync.aligned.m16n8k16.row.col.f32.f16.f16.f32 "
        "{%0,%1,%2,%3}, {%4,%5,%6,%7}, {%8,%9}, {%0,%1,%2,%3};"
        : "+f"(c[0]), "+f"(c[1]), "+f"(c[2]), "+f"(c[3])
        : "r"(a[0]), "r"(a[1]), "r"(a[2]), "r"(a[3]), "r"(b0), "r"(b1));
}

// One hidden layer (N=128, relu) for TWO M-tiles sharing each weight load.
// Streams per output K-tile: only 16 fp32 acc live; kt loop not unrolled.
template<int KP>
__device__ __forceinline__ void layer_relu2(unsigned (&d0)[8][4], unsigned (&d1)[8][4],
                                            const uint4* __restrict__ sB,
                                            const unsigned (*A0)[4],
                                            const unsigned (*A1)[4],
                                            const float* __restrict__ sbias,
                                            int t, int lane) {
#pragma unroll 1
    for (int kt = 0; kt < 8; ++kt) {
        float2 f0 = *(const float2*)(sbias + (2*kt  )*8 + 2*t);
        float2 f1 = *(const float2*)(sbias + (2*kt+1)*8 + 2*t);
        float p00[4] = {f0.x, f0.y, f0.x, f0.y};   // tile0, subtile even
        float p01[4] = {f0.x, f0.y, f0.x, f0.y};   // tile1, subtile even
        float p10[4] = {f1.x, f1.y, f1.x, f1.y};   // tile0, subtile odd
        float p11[4] = {f1.x, f1.y, f1.x, f1.y};   // tile1, subtile odd
#pragma unroll
        for (int kp = 0; kp < KP; ++kp) {
            uint4 w = sB[((2*kt)*KP + kp)*32 + lane];
            mma16816(p00, A0[2*kp],   w.x, w.y);
            mma16816(p00, A0[2*kp+1], w.z, w.w);
            mma16816(p01, A1[2*kp],   w.x, w.y);
            mma16816(p01, A1[2*kp+1], w.z, w.w);
        }
#pragma unroll
        for (int kp = 0; kp < KP; ++kp) {
            uint4 w = sB[((2*kt+1)*KP + kp)*32 + lane];
            mma16816(p10, A0[2*kp],   w.x, w.y);
            mma16816(p10, A0[2*kp+1], w.z, w.w);
            mma16816(p11, A1[2*kp],   w.x, w.y);
            mma16816(p11, A1[2*kp+1], w.z, w.w);
        }
        d0[kt][0] = pack2(fmaxf(p00[0],0.f), fmaxf(p00[1],0.f));
        d0[kt][1] = pack2(fmaxf(p00[2],0.f), fmaxf(p00[3],0.f));
        d0[kt][2] = pack2(fmaxf(p10[0],0.f), fmaxf(p10[1],0.f));
        d0[kt][3] = pack2(fmaxf(p10[2],0.f), fmaxf(p10[3],0.f));
        d1[kt][0] = pack2(fmaxf(p01[0],0.f), fmaxf(p01[1],0.f));
        d1[kt][1] = pack2(fmaxf(p01[2],0.f), fmaxf(p01[3],0.f));
        d1[kt][2] = pack2(fmaxf(p11[0],0.f), fmaxf(p11[1],0.f));
        d1[kt][3] = pack2(fmaxf(p11[2],0.f), fmaxf(p11[3],0.f));
    }
}

#define WARPS 16
#define THREADS (WARPS*32)
#define GRID 148    // one CTA per SM, single wave; warps grid-stride over chunks

__global__ __launch_bounds__(THREADS, 1)   // 65536/512 = 128 regs/thread cap
void made_main(const float* __restrict__ x, const float* __restrict__ cond,
               const float* __restrict__ b1, const float* __restrict__ b2,
               const float* __restrict__ b3,
               float* __restrict__ out_u, float* __restrict__ out_ld,
               int nChunks) {
    extern __shared__ unsigned char smem_raw[];
    uint4* sW  = (uint4*)smem_raw;
    float* sb1 = (float*)(sW + NFRAG_TOT);
    float* sb2 = sb1 + H;
    float* sb3 = sb2 + H;

    for (int i = threadIdx.x; i < NFRAG_TOT; i += blockDim.x) sW[i] = g_wfrags[i];
    if (threadIdx.x < H)    { sb1[threadIdx.x] = b1[threadIdx.x];
                              sb2[threadIdx.x] = b2[threadIdx.x]; }
    if (threadIdx.x < 2*NI)   sb3[threadIdx.x] = b3[threadIdx.x];
    __syncthreads();

    const uint4* sWcat = sW;
    const uint4* sW2f  = sW + NFRAG_CAT;
    const uint4* sW3f  = sW + NFRAG_CAT + NFRAG_W2;

    int warp = threadIdx.x >> 5;
    int lane = threadIdx.x & 31;
    int g = lane >> 2, t = lane & 3;

    int gwarp   = blockIdx.x * WARPS + warp;
    int wstride = gridDim.x * WARPS;

    // All index arithmetic in 32-bit: max offset = B*NC = 2^19*64 = 2^25 floats.
#pragma unroll 1
    for (int chunk = gwarp; chunk < nChunks; chunk += wstride) {
        int m0   = chunk * 32;           // sample row base (< 2^19)
        int xoff = m0 * NI;              // < 2^24
        int coff = m0 * NC;              // < 2^25
        const float* xb = x    + xoff;
        const float* cb = cond + coff;

        // ---- Load A1 fragments for both M-tiles (x | cond) ----
        unsigned a1[2][6][4];
#pragma unroll
        for (int ti = 0; ti < 2; ++ti) {
            const float* xt = xb + ti*16*NI;
            const float* ct = cb + ti*16*NC;
#pragma unroll
            for (int kt = 0; kt < 2; ++kt)
#pragma unroll
                for (int p = 0; p < 4; ++p) {
                    int row = g + (p & 1) * 8;
                    int col = kt*16 + 2*t + (p >> 1) * 8;
                    float2 v = *(const float2*)(xt + row*NI + col);
                    a1[ti][kt][p] = pack2(v.x, v.y);
                }
#pragma unroll
            for (int kt = 2; kt < 6; ++kt)
#pragma unroll
                for (int p = 0; p < 4; ++p) {
                    int row = g + (p & 1) * 8;
                    int col = (kt-2)*16 + 2*t + (p >> 1) * 8;
                    float2 v = *(const float2*)(ct + row*NC + col);
                    a1[ti][kt][p] = pack2(v.x, v.y);
                }
        }

        // ---- Layer 1 -> a2f, Layer 2 -> af3 (shared weight loads) ----
        unsigned a2f[2][8][4];
        layer_relu2<3>(a2f[0], a2f[1], sWcat, a1[0],  a1[1],  sb1, t, lane);
        unsigned af3[2][8][4];
        layer_relu2<4>(af3[0], af3[1], sW2f,  a2f[0], a2f[1], sb2, t, lane);

        // ---- Layer 3 + fused epilogue, per output slice nt (m=nt, a=nt+4) ----
        float sa[2][2] = {{0.f,0.f},{0.f,0.f}};   // [tile][rowhalf]
#pragma unroll 1
        for (int nt = 0; nt < 4; ++nt) {
            float2 fm = *(const float2*)(sb3 + nt*8 + 2*t);
            float2 fa = *(const float2*)(sb3 + (nt+4)*8 + 2*t);
            float am0[4] = {fm.x, fm.y, fm.x, fm.y};
            float am1[4] = {fm.x, fm.y, fm.x, fm.y};
            float aa0[4] = {fa.x, fa.y, fa.x, fa.y};
            float aa1[4] = {fa.x, fa.y, fa.x, fa.y};
#pragma unroll
            for (int kp = 0; kp < 4; ++kp) {
                uint4 wm = sW3f[(nt*4 + kp)*32 + lane];
                mma16816(am0, af3[0][2*kp],   wm.x, wm.y);
                mma16816(am0, af3[0][2*kp+1], wm.z, wm.w);
                mma16816(am1, af3[1][2*kp],   wm.x, wm.y);
                mma16816(am1, af3[1][2*kp+1], wm.z, wm.w);
            }
#pragma unroll
            for (int kp = 0; kp < 4; ++kp) {
                uint4 wa = sW3f[((nt+4)*4 + kp)*32 + lane];
                mma16816(aa0, af3[0][2*kp],   wa.x, wa.y);
                mma16816(aa0, af3[0][2*kp+1], wa.z, wa.w);
                mma16816(aa1, af3[1][2*kp],   wa.x, wa.y);
                mma16816(aa1, af3[1][2*kp+1], wa.z, wa.w);
            }
            // Epilogue slice: a=clip(a,-5,5); u=(x-m)*exp(-a)
#pragma unroll
            for (int ti = 0; ti < 2; ++ti) {
                const float* xt = xb + ti*16*NI;
                int obase = xoff + ti*16*NI;
                const float* am = ti ? am1 : am0;
                const float* aa = ti ? aa1 : aa0;
                float2 x0 = *(const float2*)(xt + g      *NI + nt*8 + 2*t);
                float2 x1 = *(const float2*)(xt + (g + 8)*NI + nt*8 + 2*t);
                float c00 = fminf(fmaxf(aa[0], -5.f), 5.f);
                float c01 = fminf(fmaxf(aa[1], -5.f), 5.f);
                float c10 = fminf(fmaxf(aa[2], -5.f), 5.f);
                float c11 = fminf(fmaxf(aa[3], -5.f), 5.f);
                float2 w0, w1;
                w0.x = (x0.x - am[0]) * __expf(-c00);
                w0.y = (x0.y - am[1]) * __expf(-c01);
                w1.x = (x1.x - am[2]) * __expf(-c10);
                w1.y = (x1.y - am[3]) * __expf(-c11);
                *(float2*)(out_u + obase + g      *NI + nt*8 + 2*t) = w0;
                *(float2*)(out_u + obase + (g + 8)*NI + nt*8 + 2*t) = w1;
                sa[ti][0] += c00 + c01;
                sa[ti][1] += c10 + c11;
            }
        }
#pragma unroll
        for (int ti = 0; ti < 2; ++ti) {
            float s0 = sa[ti][0], s1 = sa[ti][1];
            s0 += __shfl_xor_sync(0xffffffffu, s0, 1);
            s0 += __shfl_xor_sync(0xffffffffu, s0, 2);
            s1 += __shfl_xor_sync(0xffffffffu, s1, 1);
            s1 += __shfl_xor_sync(0xffffffffu, s1, 2);
            if (t == 0) {
                out_ld[m0 + ti*16 + g]     = -s0;
                out_ld[m0 + ti*16 + g + 8] = -s1;
            }
        }
    }
}

// ---------------------------------------------------------------------------
// Launch
// ---------------------------------------------------------------------------
extern "C" void kernel_launch(void* const* d_in, const int* in_sizes, int n_in,
                              void* d_out, int out_size) {
    const float* x    = (const float*)d_in[0];
    const float* cond = (const float*)d_in[1];
    const float* W1   = (const float*)d_in[2];
    const float* b1   = (const float*)d_in[3];
    const float* Wc   = (const float*)d_in[4];
    const float* W2   = (const float*)d_in[5];
    const float* b2   = (const float*)d_in[6];
    const float* W3   = (const float*)d_in[7];
    const float* b3   = (const float*)d_in[8];

    long long B = (long long)in_sizes[0] / NI;
    float* out_u  = (float*)d_out;
    float* out_ld = out_u + B * NI;
    int nChunks = (int)(B / 32);

    // Pre-pack masked weights into fragment order (tiny kernel, same stream)
    made_prep<<<(NFRAG_TOT + 127) / 128, 128>>>(W1, Wc, W2, W3);

    cudaFuncSetAttribute(made_main, cudaFuncAttributeMaxDynamicSharedMemorySize,
                         SMEM_BYTES);

    made_main<<<GRID, THREADS, SMEM_BYTES>>>(x, cond, b1, b2, b3,
                                             out_u, out_ld, nChunks);
}